// round 2
// baseline (speedup 1.0000x reference)
#include <cuda_runtime.h>
#include <math.h>
#include <stdint.h>

// Problem dims (fixed by the dataset)
#define BB 64
#define TT 1024
#define FF 256
#define UU 512
#define G4 2048   // 4*U

// ---------------- device scratch (no cudaMalloc allowed) ----------------
__device__ float g_xz[(size_t)TT * BB * G4];   // [t][b][col]  512 MB
__device__ float g_h[2][BB * UU];              // double-buffered h
__device__ unsigned g_barcount;

// ---------------- init: reset barrier + h (runs every launch) -----------
__global__ void init_kernel() {
    int i = blockIdx.x * blockDim.x + threadIdx.x;
    if (i == 0) g_barcount = 0u;
    float* p = (float*)g_h;
    for (int j = i; j < 2 * BB * UU; j += gridDim.x * blockDim.x) p[j] = 0.f;
}

// ---------------- phase 1: xz = x @ kernel + bias ------------------------
// A rows m = t*64 + b (so output is [t][b][col] contiguous per step).
#define P1_TM 128
#define P1_TN 64
#define P1_KC 16

__global__ __launch_bounds__(256) void xz_gemm(
    const float* __restrict__ x,      // [B][T][F]
    const float* __restrict__ w,      // [F][4U]
    const float* __restrict__ bias)   // [4U]
{
    __shared__ float As[P1_KC][P1_TM];  // transposed [k][m]
    __shared__ float Bs[P1_KC][P1_TN];

    const int tid = threadIdx.x;
    const int tx = tid & 15;          // n group
    const int ty = tid >> 4;          // m group
    const int m0 = ty * 8;
    const int n0 = tx * 4;
    const int mbase = blockIdx.y * P1_TM;
    const int nbase = blockIdx.x * P1_TN;

    float acc[8][4];
#pragma unroll
    for (int i = 0; i < 8; i++)
#pragma unroll
        for (int j = 0; j < 4; j++) acc[i][j] = 0.f;

    for (int kc = 0; kc < FF; kc += P1_KC) {
        // load A tile (128 rows x 16 k), transpose into As[k][m]
#pragma unroll
        for (int s = 0; s < 2; s++) {
            int idx = tid * 2 + s;          // 0..511
            int row = idx >> 2;             // 0..127
            int k4  = (idx & 3) * 4;        // 0,4,8,12
            int m = mbase + row;
            int b = m & 63;
            int t = m >> 6;
            float4 v = *(const float4*)&x[((size_t)b * TT + t) * FF + kc + k4];
            As[k4 + 0][row] = v.x;
            As[k4 + 1][row] = v.y;
            As[k4 + 2][row] = v.z;
            As[k4 + 3][row] = v.w;
        }
        // load B tile (16 k x 64 n)
        {
            int row = tid >> 4;             // 0..15
            int cq  = tid & 15;             // 0..15
            float4 v = *(const float4*)&w[(size_t)(kc + row) * G4 + nbase + cq * 4];
            *(float4*)&Bs[row][cq * 4] = v;
        }
        __syncthreads();

#pragma unroll
        for (int k = 0; k < P1_KC; k++) {
            float4 a0 = *(const float4*)&As[k][m0];
            float4 a1 = *(const float4*)&As[k][m0 + 4];
            float4 bv = *(const float4*)&Bs[k][n0];
            float a[8] = {a0.x, a0.y, a0.z, a0.w, a1.x, a1.y, a1.z, a1.w};
            float bb[4] = {bv.x, bv.y, bv.z, bv.w};
#pragma unroll
            for (int i = 0; i < 8; i++)
#pragma unroll
                for (int j = 0; j < 4; j++)
                    acc[i][j] = fmaf(a[i], bb[j], acc[i][j]);
        }
        __syncthreads();
    }

    float4 bv = *(const float4*)&bias[nbase + n0];
#pragma unroll
    for (int i = 0; i < 8; i++) {
        float4 o;
        o.x = acc[i][0] + bv.x;
        o.y = acc[i][1] + bv.y;
        o.z = acc[i][2] + bv.z;
        o.w = acc[i][3] + bv.w;
        *(float4*)&g_xz[(size_t)(mbase + m0 + i) * G4 + nbase + n0] = o;
    }
}

// ---------------- phase 2: persistent recurrent kernel -------------------
// 128 CTAs, 1/SM (SMEM-bound) -> co-resident, safe global barrier.
// CTA j owns units [4j, 4j+4): columns gate*512 + 4j + uu for 4 gates.
// Warp w handles batches [8w, 8w+8). Lane: c = lane&15 (col), khalf = lane>>4.
#define NCTA2 128
#define THR2  256
#define WPAD  516   // padded k-stride for W slice (conflict-free LDS.128)

__global__ __launch_bounds__(THR2, 1) void lstm_rec(
    const float* __restrict__ R,    // [512][2048]
    float* __restrict__ out)        // [B][T][U]
{
    extern __shared__ float smem[];
    float* Ws = smem;                   // [16][WPAD]
    float* Hs = smem + 16 * WPAD;       // [64][512]

    const int tid  = threadIdx.x;
    const int lane = tid & 31;
    const int warp = tid >> 5;
    const int cta  = blockIdx.x;
    const int u0   = cta * 4;

    // Load recurrent-weight slice: Ws[c][k] = R[k][gate*512 + u0 + uu]
    for (int idx = tid; idx < 16 * UU; idx += THR2) {
        int c = idx & 15;
        int k = idx >> 4;
        int gate = c >> 2, uu = c & 3;
        Ws[c * WPAD + k] = R[(size_t)k * G4 + gate * 512 + u0 + uu];
    }

    const int c      = lane & 15;
    const int khalf  = lane >> 4;
    const int kbeg   = khalf * 256;
    const int gate   = c >> 2;
    const int uu     = c & 3;
    const int colg   = gate * 512 + u0 + uu;
    const int uglob  = u0 + uu;
    const int b0     = warp * 8;
    const bool gate0 = ((lane & 12) == 0) && (khalf == 0);  // lanes 0..3 finalize

    float cstate[8];
#pragma unroll
    for (int i = 0; i < 8; i++) cstate[i] = 0.f;

    const float* Wc = &Ws[c * WPAD + kbeg];

    for (int t = 0; t < TT; t++) {
        const int p = t & 1;

        // load h[p] (written by other SMs) -> SMEM, L2 path (L1 incoherent)
        {
            const float4* src = (const float4*)g_h[p];
            float4* dst = (float4*)Hs;
#pragma unroll 4
            for (int i = tid; i < BB * UU / 4; i += THR2)
                dst[i] = __ldcg(&src[i]);
        }
        __syncthreads();

        // prefetch xz for this step (consumed in epilogue)
        float xzv[8];
        const float* xzt = &g_xz[(size_t)t * BB * G4];
#pragma unroll
        for (int i = 0; i < 8; i++) xzv[i] = __ldcg(&xzt[(b0 + i) * G4 + colg]);

        // GEMM: acc[i] = sum_k Hs[b0+i][kbeg+k] * Wc[k], k in [0,256)
        float acc[8];
#pragma unroll
        for (int i = 0; i < 8; i++) acc[i] = 0.f;

#pragma unroll 2
        for (int k = 0; k < 256; k += 8) {
            float4 w0 = *(const float4*)&Wc[k];
            float4 w1 = *(const float4*)&Wc[k + 4];
#pragma unroll
            for (int i = 0; i < 8; i++) {
                const float* hr = &Hs[(b0 + i) * UU + kbeg + k];
                float4 h0 = *(const float4*)&hr[0];
                float4 h1 = *(const float4*)&hr[4];
                float a = acc[i];
                a = fmaf(h0.x, w0.x, a);
                a = fmaf(h0.y, w0.y, a);
                a = fmaf(h0.z, w0.z, a);
                a = fmaf(h0.w, w0.w, a);
                a = fmaf(h1.x, w1.x, a);
                a = fmaf(h1.y, w1.y, a);
                a = fmaf(h1.z, w1.z, a);
                a = fmaf(h1.w, w1.w, a);
                acc[i] = a;
            }
        }

        // combine the two K-halves (lane ^ 16)
        float z[8];
#pragma unroll
        for (int i = 0; i < 8; i++) {
            float s = acc[i] + __shfl_xor_sync(0xffffffffu, acc[i], 16);
            z[i] = s + xzv[i];
        }

        // gather f/g/o gates into the i-gate lanes (c -> c+4, c+8, c+12)
        float zf[8], zg[8], zo[8];
#pragma unroll
        for (int i = 0; i < 8; i++) {
            zf[i] = __shfl_sync(0xffffffffu, z[i], lane + 4);
            zg[i] = __shfl_sync(0xffffffffu, z[i], lane + 8);
            zo[i] = __shfl_sync(0xffffffffu, z[i], lane + 12);
        }

        if (gate0) {
            float* ghn = g_h[p ^ 1];
#pragma unroll
            for (int i = 0; i < 8; i++) {
                float ig = 1.f / (1.f + __expf(-z[i]));
                float fg = 1.f / (1.f + __expf(-zf[i]));
                float og = 1.f / (1.f + __expf(-zo[i]));
                cstate[i] = fg * cstate[i] + ig * zg[i];
                float h = og * cstate[i];
                ghn[(b0 + i) * UU + uglob] = h;
                out[((size_t)(b0 + i) * TT + t) * UU + uglob] = tanhf(h);
            }
        }

        // ---- grid barrier (monotonic counter; reset by init each launch) ----
        __syncthreads();
        if (tid == 0) {
            __threadfence();
            unsigned arrived = atomicAdd(&g_barcount, 1u) + 1u;
            unsigned target = (unsigned)(t + 1) * (unsigned)gridDim.x;
            if (arrived < target) {
                while (*((volatile unsigned*)&g_barcount) < target) { }
            }
        }
        __syncthreads();
    }
}

// ---------------- launch ----------------
extern "C" void kernel_launch(void* const* d_in, const int* in_sizes, int n_in,
                              void* d_out, int out_size) {
    const float* x    = (const float*)d_in[0];   // [64,1024,256]
    const float* w    = (const float*)d_in[1];   // [256,2048]
    const float* rw   = (const float*)d_in[2];   // [512,2048]
    const float* bias = (const float*)d_in[3];   // [2048]
    float* out = (float*)d_out;                  // [64,1024,512]

    (void)in_sizes; (void)n_in; (void)out_size;

    // phase 0: reset persistent state (graph-replay safe)
    init_kernel<<<64, 256>>>();

    // phase 1: xz = x @ kernel + bias
    dim3 g1(G4 / P1_TN, (BB * TT) / P1_TM);  // (32, 512)
    xz_gemm<<<g1, 256>>>(x, w, bias);

    // phase 2: recurrence (persistent, needs >48KB dynamic SMEM)
    static int smem_set = 0;
    const int smem_bytes = (16 * WPAD + BB * UU) * (int)sizeof(float); // ~160 KB
    if (!smem_set) {
        cudaFuncSetAttribute(lstm_rec, cudaFuncAttributeMaxDynamicSharedMemorySize,
                             smem_bytes);
        smem_set = 1;
    }
    lstm_rec<<<NCTA2, THR2, smem_bytes>>>(rw, out);
}

// round 3
// speedup vs baseline: 1.2206x; 1.2206x over previous
#include <cuda_runtime.h>
#include <math.h>
#include <stdint.h>

// Problem dims (fixed by the dataset)
#define BB 64
#define TT 1024
#define FF 256
#define UU 512
#define G4 2048   // 4*U

// ---------------- device scratch (no cudaMalloc allowed) ----------------
__device__ float g_xz[(size_t)TT * BB * G4];   // [t][b][col]  512 MB
__device__ float g_h[2][BB * UU];              // double-buffered h
__device__ unsigned g_barcount;

// ---------------- init: reset barrier + h (runs every launch) -----------
__global__ void init_kernel() {
    int i = blockIdx.x * blockDim.x + threadIdx.x;
    if (i == 0) g_barcount = 0u;
    float* p = (float*)g_h;
    for (int j = i; j < 2 * BB * UU; j += gridDim.x * blockDim.x) p[j] = 0.f;
}

// ---------------- phase 1: xz = x @ kernel + bias ------------------------
// A rows m = t*64 + b (so output is [t][b][col] contiguous per step).
#define P1_TM 128
#define P1_TN 64
#define P1_KC 16

__global__ __launch_bounds__(256) void xz_gemm(
    const float* __restrict__ x,      // [B][T][F]
    const float* __restrict__ w,      // [F][4U]
    const float* __restrict__ bias)   // [4U]
{
    __shared__ float As[P1_KC][P1_TM];  // transposed [k][m]
    __shared__ float Bs[P1_KC][P1_TN];

    const int tid = threadIdx.x;
    const int tx = tid & 15;          // n group
    const int ty = tid >> 4;          // m group
    const int m0 = ty * 8;
    const int n0 = tx * 4;
    const int mbase = blockIdx.y * P1_TM;
    const int nbase = blockIdx.x * P1_TN;

    float acc[8][4];
#pragma unroll
    for (int i = 0; i < 8; i++)
#pragma unroll
        for (int j = 0; j < 4; j++) acc[i][j] = 0.f;

    for (int kc = 0; kc < FF; kc += P1_KC) {
        // load A tile (128 rows x 16 k), transpose into As[k][m]
#pragma unroll
        for (int s = 0; s < 2; s++) {
            int idx = tid * 2 + s;          // 0..511
            int row = idx >> 2;             // 0..127
            int k4  = (idx & 3) * 4;        // 0,4,8,12
            int m = mbase + row;
            int b = m & 63;
            int t = m >> 6;
            float4 v = *(const float4*)&x[((size_t)b * TT + t) * FF + kc + k4];
            As[k4 + 0][row] = v.x;
            As[k4 + 1][row] = v.y;
            As[k4 + 2][row] = v.z;
            As[k4 + 3][row] = v.w;
        }
        // load B tile (16 k x 64 n)
        {
            int row = tid >> 4;             // 0..15
            int cq  = tid & 15;             // 0..15
            float4 v = *(const float4*)&w[(size_t)(kc + row) * G4 + nbase + cq * 4];
            *(float4*)&Bs[row][cq * 4] = v;
        }
        __syncthreads();

#pragma unroll
        for (int k = 0; k < P1_KC; k++) {
            float4 a0 = *(const float4*)&As[k][m0];
            float4 a1 = *(const float4*)&As[k][m0 + 4];
            float4 bv = *(const float4*)&Bs[k][n0];
            float a[8] = {a0.x, a0.y, a0.z, a0.w, a1.x, a1.y, a1.z, a1.w};
            float bb[4] = {bv.x, bv.y, bv.z, bv.w};
#pragma unroll
            for (int i = 0; i < 8; i++)
#pragma unroll
                for (int j = 0; j < 4; j++)
                    acc[i][j] = fmaf(a[i], bb[j], acc[i][j]);
        }
        __syncthreads();
    }

    float4 bv = *(const float4*)&bias[nbase + n0];
#pragma unroll
    for (int i = 0; i < 8; i++) {
        float4 o;
        o.x = acc[i][0] + bv.x;
        o.y = acc[i][1] + bv.y;
        o.z = acc[i][2] + bv.z;
        o.w = acc[i][3] + bv.w;
        *(float4*)&g_xz[(size_t)(mbase + m0 + i) * G4 + nbase + n0] = o;
    }
}

// ---------------- phase 2: persistent recurrent kernel -------------------
// 128 CTAs, 1/SM (SMEM-bound) -> co-resident, safe global barrier.
// CTA j owns units [4j, 4j+4): columns gate*512 + 4j + uu for 4 gates.
// 512 threads = 16 warps; warp w handles batches [4w, 4w+4) -- its h rows are
// warp-private, so staging needs only __syncwarp (no CTA sync before GEMM).
// Lane: c = lane&15 (col), khalf = lane>>4 (K split in halves of 256).
#define NCTA2 128
#define THR2  512
#define WPAD  516   // padded k-stride for W slice

// cp.async.cg: 16B global->shared, L1-bypassed (L2-coherent; h is cross-SM).
__device__ __forceinline__ void cp_async16_cg(uint32_t saddr, const void* gaddr) {
    asm volatile("cp.async.cg.shared.global [%0], [%1], 16;"
                 :: "r"(saddr), "l"(gaddr));
}

__global__ __launch_bounds__(THR2, 1) void lstm_rec(
    const float* __restrict__ R,    // [512][2048]
    float* __restrict__ out)        // [B][T][U]
{
    extern __shared__ float smem[];
    float* Ws = smem;                   // [16][WPAD]
    float* Hs = smem + 16 * WPAD;       // [64][512]

    const int tid  = threadIdx.x;
    const int lane = tid & 31;
    const int warp = tid >> 5;
    const int cta  = blockIdx.x;
    const int u0   = cta * 4;

    // Load recurrent-weight slice: Ws[c][k] = R[k][gate*512 + u0 + uu]
    for (int idx = tid; idx < 16 * UU; idx += THR2) {
        int c = idx & 15;
        int k = idx >> 4;
        int gate = c >> 2, uu = c & 3;
        Ws[c * WPAD + k] = R[(size_t)k * G4 + gate * 512 + u0 + uu];
    }
    __syncthreads();

    const int c      = lane & 15;
    const int khalf  = lane >> 4;
    const int kbeg   = khalf * 256;
    const int gate   = c >> 2;
    const int uu     = c & 3;
    const int colg   = gate * 512 + u0 + uu;
    const int uglob  = u0 + uu;
    const int b0     = warp * 4;
    const bool gate0 = (lane < 4);      // lanes 0..3 finalize (c<4, khalf=0)

    float cstate[4];
#pragma unroll
    for (int i = 0; i < 4; i++) cstate[i] = 0.f;

    const float* Wc = &Ws[c * WPAD + kbeg];
    float* Hw = &Hs[b0 * UU];           // warp-private 4 rows

    // smem byte address for this lane's cp.async destinations
    uint32_t hw_saddr;
    asm("{ .reg .u64 t; cvta.to.shared.u64 t, %1; cvt.u32.u64 %0, t; }"
        : "=r"(hw_saddr) : "l"(Hw + lane * 4));

    for (int t = 0; t < TT; t++) {
        const int p = t & 1;

        // prefetch xz for this step (independent of h; issue first)
        float xzv[4];
        const float* xzt = &g_xz[(size_t)t * BB * G4];
#pragma unroll
        for (int i = 0; i < 4; i++) xzv[i] = __ldcg(&xzt[(b0 + i) * G4 + colg]);

        // warp-private h staging: 4 rows * 512 floats = 512 float4; 16/lane.
        // cp.async.cg -> register-free, L1-bypassed.
        {
            const float4* src = (const float4*)&g_h[p][b0 * UU] + lane;
#pragma unroll
            for (int i = 0; i < 16; i++)
                cp_async16_cg(hw_saddr + (uint32_t)(i * 32 * 16),
                              (const void*)(src + i * 32));
            asm volatile("cp.async.commit_group;");
            asm volatile("cp.async.wait_group 0;" ::: "memory");
            __syncwarp();
        }

        // GEMM: acc[i] = sum_k Hw[i][kbeg+k] * Wc[k], k in [0,256)
        float acc[4];
#pragma unroll
        for (int i = 0; i < 4; i++) acc[i] = 0.f;

#pragma unroll 4
        for (int k = 0; k < 256; k += 8) {
            float4 w0 = *(const float4*)&Wc[k];
            float4 w1 = *(const float4*)&Wc[k + 4];
#pragma unroll
            for (int i = 0; i < 4; i++) {
                const float* hr = &Hw[i * UU + kbeg + k];
                float4 h0 = *(const float4*)&hr[0];
                float4 h1 = *(const float4*)&hr[4];
                float a = acc[i];
                a = fmaf(h0.x, w0.x, a);
                a = fmaf(h0.y, w0.y, a);
                a = fmaf(h0.z, w0.z, a);
                a = fmaf(h0.w, w0.w, a);
                a = fmaf(h1.x, w1.x, a);
                a = fmaf(h1.y, w1.y, a);
                a = fmaf(h1.z, w1.z, a);
                a = fmaf(h1.w, w1.w, a);
                acc[i] = a;
            }
        }

        // combine the two K-halves (lane ^ 16)
        float z[4];
#pragma unroll
        for (int i = 0; i < 4; i++) {
            float s = acc[i] + __shfl_xor_sync(0xffffffffu, acc[i], 16);
            z[i] = s + xzv[i];
        }

        // gather f/g/o gates into the i-gate lanes (c -> c+4, c+8, c+12)
        float zf[4], zg[4], zo[4];
#pragma unroll
        for (int i = 0; i < 4; i++) {
            zf[i] = __shfl_sync(0xffffffffu, z[i], lane + 4);
            zg[i] = __shfl_sync(0xffffffffu, z[i], lane + 8);
            zo[i] = __shfl_sync(0xffffffffu, z[i], lane + 12);
        }

        if (gate0) {
            float* ghn = g_h[p ^ 1];
#pragma unroll
            for (int i = 0; i < 4; i++) {
                float ig = 1.f / (1.f + __expf(-z[i]));
                float fg = 1.f / (1.f + __expf(-zf[i]));
                float og = 1.f / (1.f + __expf(-zo[i]));
                cstate[i] = fg * cstate[i] + ig * zg[i];
                float h = og * cstate[i];
                ghn[(b0 + i) * UU + uglob] = h;
                out[((size_t)(b0 + i) * TT + t) * UU + uglob] = tanhf(h);
            }
        }

        // ---- grid barrier (monotonic counter; reset by init each launch) ----
        __syncthreads();
        if (tid == 0) {
            __threadfence();
            unsigned arrived = atomicAdd(&g_barcount, 1u) + 1u;
            unsigned target = (unsigned)(t + 1) * (unsigned)gridDim.x;
            if (arrived < target) {
                while (*((volatile unsigned*)&g_barcount) < target) { }
            }
        }
        __syncthreads();
    }
}

// ---------------- launch ----------------
extern "C" void kernel_launch(void* const* d_in, const int* in_sizes, int n_in,
                              void* d_out, int out_size) {
    const float* x    = (const float*)d_in[0];   // [64,1024,256]
    const float* w    = (const float*)d_in[1];   // [256,2048]
    const float* rw   = (const float*)d_in[2];   // [512,2048]
    const float* bias = (const float*)d_in[3];   // [2048]
    float* out = (float*)d_out;                  // [64,1024,512]

    (void)in_sizes; (void)n_in; (void)out_size;

    // phase 0: reset persistent state (graph-replay safe)
    init_kernel<<<64, 256>>>();

    // phase 1: xz = x @ kernel + bias
    dim3 g1(G4 / P1_TN, (BB * TT) / P1_TM);  // (32, 512)
    xz_gemm<<<g1, 256>>>(x, w, bias);

    // phase 2: recurrence (persistent, needs >48KB dynamic SMEM)
    static int smem_set = 0;
    const int smem_bytes = (16 * WPAD + BB * UU) * (int)sizeof(float); // ~160 KB
    if (!smem_set) {
        cudaFuncSetAttribute(lstm_rec, cudaFuncAttributeMaxDynamicSharedMemorySize,
                             smem_bytes);
        smem_set = 1;
    }
    lstm_rec<<<NCTA2, THR2, smem_bytes>>>(rw, out);
}

// round 5
// speedup vs baseline: 1.6052x; 1.3150x over previous
#include <cuda_runtime.h>
#include <cuda_bf16.h>
#include <math.h>
#include <stdint.h>

// Problem dims (fixed by the dataset)
#define BB 64
#define TT 1024
#define FF 256
#define UU 512
#define G4 2048   // 4*U

#define NCTA 128          // phase-2 CTAs (1/SM, co-resident)
#define THR2 512          // 16 warps

// ---------------- device scratch (no cudaMalloc allowed) ----------------
__device__ float g_xz[(size_t)TT * BB * G4];                 // [t][b][col]
// h broadcast: [parity][hi/lo][b*512] bf16
__device__ __align__(16) __nv_bfloat16 g_hbuf[2][2][BB * UU];
// per-CTA pre-fragmented recurrent weights: 8192 words each
// word idx = (((plane*2 + nt)*32 + kt)*32 + lane)*2 + w2
__device__ __align__(16) uint32_t g_Bfrag[NCTA][8192];
__device__ unsigned g_barcount;

// ---------------- helpers ----------------
__device__ __forceinline__ uint32_t smem_u32(const void* p) {
    uint32_t a;
    asm("{ .reg .u64 t; cvta.to.shared.u64 t, %1; cvt.u32.u64 %0, t; }"
        : "=r"(a) : "l"(p));
    return a;
}
__device__ __forceinline__ void cp_async16(uint32_t saddr, const void* gaddr) {
    asm volatile("cp.async.cg.shared.global [%0], [%1], 16;" :: "r"(saddr), "l"(gaddr));
}
#define CP_COMMIT() asm volatile("cp.async.commit_group;")
#define CP_WAIT0()  asm volatile("cp.async.wait_group 0;" ::: "memory")

__device__ __forceinline__ void mma_bf16(float c[4], uint32_t a0, uint32_t a1,
                                         uint32_t a2, uint32_t a3,
                                         uint32_t b0, uint32_t b1) {
    asm volatile(
        "mma.sync.aligned.m16n8k16.row.col.f32.bf16.bf16.f32 "
        "{%0,%1,%2,%3}, {%4,%5,%6,%7}, {%8,%9}, {%0,%1,%2,%3};"
        : "+f"(c[0]), "+f"(c[1]), "+f"(c[2]), "+f"(c[3])
        : "r"(a0), "r"(a1), "r"(a2), "r"(a3), "r"(b0), "r"(b1));
}

// ---------------- init: reset barrier + h buffers ----------------
__global__ void init_kernel() {
    int i = blockIdx.x * blockDim.x + threadIdx.x;
    if (i == 0) g_barcount = 0u;
    uint32_t* p = (uint32_t*)g_hbuf;  // 2*2*64*512 bf16 = 65536 words
    for (int j = i; j < 65536; j += gridDim.x * blockDim.x) p[j] = 0u;
}

// ---------------- prep: split R into per-CTA, per-lane mma fragments -----
// CTA j owns units [4j,4j+4). Local col n = gate*4+u -> global gate*512+4j+u.
// B fragment layout (m16n8k16 .row.col): lane g=l>>2,t=l&3 holds
//   b0={B[k=kt*16+t*2][n=nt*8+g], B[k+1][n]}, b1={B[k+8][n], B[k+9][n]}
__global__ void prep_B(const float* __restrict__ R) {
    const int j = blockIdx.x;
    uint32_t* dst = g_Bfrag[j];
    for (int widx = threadIdx.x; widx < 8192; widx += blockDim.x) {
        int w2    = widx & 1;
        int lane  = (widx >> 1) & 31;
        int kt    = (widx >> 6) & 31;
        int nt    = (widx >> 11) & 1;
        int plane = widx >> 12;
        int g = lane >> 2, t = lane & 3;
        int k = kt * 16 + t * 2 + w2 * 8;
        int n = nt * 8 + g;
        int col = (n >> 2) * 512 + j * 4 + (n & 3);
        float v0 = R[(size_t)k * G4 + col];
        float v1 = R[(size_t)(k + 1) * G4 + col];
        uint16_t h0, h1;
        if (plane == 0) {
            __nv_bfloat16 b0 = __float2bfloat16(v0);
            __nv_bfloat16 b1 = __float2bfloat16(v1);
            h0 = *(uint16_t*)&b0; h1 = *(uint16_t*)&b1;
        } else {
            __nv_bfloat16 t0 = __float2bfloat16(v0);
            __nv_bfloat16 t1 = __float2bfloat16(v1);
            __nv_bfloat16 b0 = __float2bfloat16(v0 - __bfloat162float(t0));
            __nv_bfloat16 b1 = __float2bfloat16(v1 - __bfloat162float(t1));
            h0 = *(uint16_t*)&b0; h1 = *(uint16_t*)&b1;
        }
        dst[widx] = ((uint32_t)h1 << 16) | h0;
    }
}

// ---------------- phase 1: xz = x @ kernel + bias (SIMT, known-good) -----
#define P1_TM 128
#define P1_TN 64
#define P1_KC 16

__global__ __launch_bounds__(256) void xz_gemm(
    const float* __restrict__ x, const float* __restrict__ w,
    const float* __restrict__ bias)
{
    __shared__ float As[P1_KC][P1_TM];
    __shared__ float Bs[P1_KC][P1_TN];

    const int tid = threadIdx.x;
    const int tx = tid & 15, ty = tid >> 4;
    const int m0 = ty * 8, n0 = tx * 4;
    const int mbase = blockIdx.y * P1_TM, nbase = blockIdx.x * P1_TN;

    float acc[8][4];
#pragma unroll
    for (int i = 0; i < 8; i++)
#pragma unroll
        for (int jj = 0; jj < 4; jj++) acc[i][jj] = 0.f;

    for (int kc = 0; kc < FF; kc += P1_KC) {
#pragma unroll
        for (int s = 0; s < 2; s++) {
            int idx = tid * 2 + s;
            int row = idx >> 2;
            int k4 = (idx & 3) * 4;
            int m = mbase + row;
            int b = m & 63, t = m >> 6;
            float4 v = *(const float4*)&x[((size_t)b * TT + t) * FF + kc + k4];
            As[k4 + 0][row] = v.x; As[k4 + 1][row] = v.y;
            As[k4 + 2][row] = v.z; As[k4 + 3][row] = v.w;
        }
        {
            int row = tid >> 4, cq = tid & 15;
            float4 v = *(const float4*)&w[(size_t)(kc + row) * G4 + nbase + cq * 4];
            *(float4*)&Bs[row][cq * 4] = v;
        }
        __syncthreads();
#pragma unroll
        for (int k = 0; k < P1_KC; k++) {
            float4 a0 = *(const float4*)&As[k][m0];
            float4 a1 = *(const float4*)&As[k][m0 + 4];
            float4 bv = *(const float4*)&Bs[k][n0];
            float a[8] = {a0.x, a0.y, a0.z, a0.w, a1.x, a1.y, a1.z, a1.w};
            float bb4[4] = {bv.x, bv.y, bv.z, bv.w};
#pragma unroll
            for (int i = 0; i < 8; i++)
#pragma unroll
                for (int jj = 0; jj < 4; jj++)
                    acc[i][jj] = fmaf(a[i], bb4[jj], acc[i][jj]);
        }
        __syncthreads();
    }
    float4 bv = *(const float4*)&bias[nbase + n0];
#pragma unroll
    for (int i = 0; i < 8; i++) {
        float4 o;
        o.x = acc[i][0] + bv.x; o.y = acc[i][1] + bv.y;
        o.z = acc[i][2] + bv.z; o.w = acc[i][3] + bv.w;
        *(float4*)&g_xz[(size_t)(mbase + m0 + i) * G4 + nbase + n0] = o;
    }
}

// ---------------- phase 2: persistent mma.sync recurrence ----------------
// SMEM map (bytes, relative to dynamic base):
#define H_STRIDE   1040                 // 520 bf16/row -> conflict-free frags
#define SM_HHI     0
#define SM_HLO     66560                // 64*1040
#define SM_B       133120
#define SM_Z       165888               // zbuf: [2][64][20] f32
#define Z_STRIDE_W 20
#define SMEM_DYN   176128

__global__ __launch_bounds__(THR2, 1) void lstm_rec(float* __restrict__ out)
{
    extern __shared__ char sm[];
    const int tid  = threadIdx.x;
    const int lane = tid & 31;
    const int warp = tid >> 5;
    const int cta  = blockIdx.x;

    const uint32_t smBase = smem_u32(sm);

    // ---- load resident B fragments (32KB) ----
    {
        const uint32_t* src = g_Bfrag[cta];
        for (int i = tid; i < 8192 / 4; i += THR2)
            cp_async16(smBase + SM_B + i * 16, src + i * 4);
        CP_COMMIT(); CP_WAIT0();
    }
    __syncthreads();

    // ---- per-thread h-staging granule offsets (k-half split by warp group)
    const int lt = tid & 255;
    const int kbase = (tid < 256) ? 0 : 32;     // k8 base for this thread
    int srcOff[8], dstOff[8];
#pragma unroll
    for (int i = 0; i < 8; i++) {
        int g = lt + i * 256;       // 0..2047
        int row = g >> 5;
        int k8 = (g & 31) + kbase;
        srcOff[i] = row * 512 + k8 * 8;         // elements
        dstOff[i] = row * H_STRIDE + k8 * 16;   // bytes
    }

    // ---- warp mma assignment ----
    const int isHigh = warp >> 3;               // k-half
    const int combo  = warp & 7;
    const int mt = combo & 3, nt = combo >> 1 >> 1; // nt = combo>>2
    const int g  = lane >> 2, tq = lane & 3;
    const int aoff  = (mt * 16 + g) * H_STRIDE + tq * 4;
    const char* bBaseHi = sm + SM_B + ((0 * 2 + nt) * 32) * 256 + lane * 8;
    const char* bBaseLo = sm + SM_B + ((1 * 2 + nt) * 32) * 256 + lane * 8;
    float* zb = (float*)(sm + SM_Z);

    // epilogue constants (threads 0..63 <-> batch b)
    float cst[4] = {0.f, 0.f, 0.f, 0.f};

    for (int t = 0; t < TT; t++) {
        const int p = t & 1;

        // xz prefetch for epilogue threads (latency hidden under mma)
        float4 xz4[4];
        if (tid < 64) {
            const float* xzt = &g_xz[((size_t)t * BB + tid) * G4 + cta * 4];
#pragma unroll
            for (int gate = 0; gate < 4; gate++)
                xz4[gate] = *(const float4*)&xzt[gate * 512];
        }

        // stage this thread's k-half of h (hi+lo) into SMEM
        {
            const __nv_bfloat16* hhi = g_hbuf[p][0];
            const __nv_bfloat16* hlo = g_hbuf[p][1];
#pragma unroll
            for (int i = 0; i < 8; i++) {
                cp_async16(smBase + SM_HHI + dstOff[i], hhi + srcOff[i]);
                cp_async16(smBase + SM_HLO + dstOff[i], hlo + srcOff[i]);
            }
            CP_COMMIT(); CP_WAIT0();
        }
        // k-half group barrier: low warps (threads 0-255) id 3, high id 4.
        if (!isHigh) asm volatile("bar.sync 3, 256;" ::: "memory");
        else         asm volatile("bar.sync 4, 256;" ::: "memory");

        // ---- 3-pass split MMA over this warp's k-half (16 ktiles) ----
        float c[4] = {0.f, 0.f, 0.f, 0.f};
#pragma unroll
        for (int pass = 0; pass < 3; pass++) {
            const char* aB = sm + ((pass == 2) ? SM_HLO : SM_HHI) + aoff;
            const char* bB = (pass == 1) ? bBaseLo : bBaseHi;
#pragma unroll
            for (int ktl = 0; ktl < 16; ktl++) {
                int kt = isHigh * 16 + ktl;
                int ka = kt * 32;
                uint32_t a0 = *(const uint32_t*)(aB + ka);
                uint32_t a1 = *(const uint32_t*)(aB + ka + 8 * H_STRIDE);
                uint32_t a2 = *(const uint32_t*)(aB + ka + 16);
                uint32_t a3 = *(const uint32_t*)(aB + ka + 8 * H_STRIDE + 16);
                uint2 b = *(const uint2*)(bB + kt * 256);
                mma_bf16(c, a0, a1, a2, a3, b.x, b.y);
            }
        }

        // store partials: zbuf[khalf][row][col]
        {
            int r = mt * 16 + g, cc = nt * 8 + tq * 2;
            float2 v01 = {c[0], c[1]};
            float2 v23 = {c[2], c[3]};
            *(float2*)&zb[(isHigh * 64 + r) * Z_STRIDE_W + cc] = v01;
            *(float2*)&zb[(isHigh * 64 + r + 8) * Z_STRIDE_W + cc] = v23;
        }
        __syncthreads();

        // ---- epilogue: threads 0..63, one per batch ----
        if (tid < 64) {
            const int b = tid;
            float4 q[4];
#pragma unroll
            for (int gate = 0; gate < 4; gate++) {
                float4 z0 = *(const float4*)&zb[b * Z_STRIDE_W + gate * 4];
                float4 z1 = *(const float4*)&zb[(64 + b) * Z_STRIDE_W + gate * 4];
                q[gate].x = z0.x + z1.x + xz4[gate].x;
                q[gate].y = z0.y + z1.y + xz4[gate].y;
                q[gate].z = z0.z + z1.z + xz4[gate].z;
                q[gate].w = z0.w + z1.w + xz4[gate].w;
            }
            float zi[4] = {q[0].x, q[0].y, q[0].z, q[0].w};
            float zf[4] = {q[1].x, q[1].y, q[1].z, q[1].w};
            float zg[4] = {q[2].x, q[2].y, q[2].z, q[2].w};
            float zo[4] = {q[3].x, q[3].y, q[3].z, q[3].w};
            uint16_t hh[4], hl[4];
            float ov[4];
#pragma unroll
            for (int u = 0; u < 4; u++) {
                float ig = 1.f / (1.f + __expf(-zi[u]));
                float fg = 1.f / (1.f + __expf(-zf[u]));
                float og = 1.f / (1.f + __expf(-zo[u]));
                cst[u] = fg * cst[u] + ig * zg[u];
                float h = og * cst[u];
                __nv_bfloat16 bh = __float2bfloat16(h);
                __nv_bfloat16 bl = __float2bfloat16(h - __bfloat162float(bh));
                hh[u] = *(uint16_t*)&bh;
                hl[u] = *(uint16_t*)&bl;
                ov[u] = tanhf(h);
            }
            uint2 vhi, vlo;
            vhi.x = ((uint32_t)hh[1] << 16) | hh[0];
            vhi.y = ((uint32_t)hh[3] << 16) | hh[2];
            vlo.x = ((uint32_t)hl[1] << 16) | hl[0];
            vlo.y = ((uint32_t)hl[3] << 16) | hl[2];
            const int pn = p ^ 1;
            __stcg((uint2*)&g_hbuf[pn][0][b * UU + cta * 4], vhi);
            __stcg((uint2*)&g_hbuf[pn][1][b * UU + cta * 4], vlo);
            float4 o4 = {ov[0], ov[1], ov[2], ov[3]};
            *(float4*)&out[((size_t)b * TT + t) * UU + cta * 4] = o4;
        }

        // ---- grid barrier (monotonic counter) ----
        __syncthreads();
        if (tid == 0) {
            __threadfence();
            unsigned arrived = atomicAdd(&g_barcount, 1u) + 1u;
            unsigned target = (unsigned)(t + 1) * (unsigned)NCTA;
            if (arrived < target) {
                while (*((volatile unsigned*)&g_barcount) < target) { }
            }
        }
        __syncthreads();
    }
}

// ---------------- launch ----------------
extern "C" void kernel_launch(void* const* d_in, const int* in_sizes, int n_in,
                              void* d_out, int out_size) {
    const float* x    = (const float*)d_in[0];   // [64,1024,256]
    const float* w    = (const float*)d_in[1];   // [256,2048]
    const float* rw   = (const float*)d_in[2];   // [512,2048]
    const float* bias = (const float*)d_in[3];   // [2048]
    float* out = (float*)d_out;                  // [64,1024,512]
    (void)in_sizes; (void)n_in; (void)out_size;

    init_kernel<<<64, 256>>>();
    prep_B<<<NCTA, 256>>>(rw);

    dim3 g1(G4 / P1_TN, (BB * TT) / P1_TM);
    xz_gemm<<<g1, 256>>>(x, w, bias);

    static int smem_set = 0;
    if (!smem_set) {
        cudaFuncSetAttribute(lstm_rec, cudaFuncAttributeMaxDynamicSharedMemorySize,
                             SMEM_DYN);
        smem_set = 1;
    }
    lstm_rec<<<NCTA, THR2, SMEM_DYN>>>(out);
}

// round 6
// speedup vs baseline: 1.9399x; 1.2086x over previous
#include <cuda_runtime.h>
#include <cuda_bf16.h>
#include <math.h>
#include <stdint.h>

// Problem dims (fixed by the dataset)
#define BB 64
#define TT 1024
#define FF 256
#define UU 512
#define G4 2048   // 4*U

#define NCTA 128          // phase-2 CTAs (1/SM, co-resident)
#define THR2 512          // 16 warps

// ---------------- device scratch (no cudaMalloc allowed) ----------------
__device__ float g_xz[(size_t)TT * BB * G4];                 // [t][b][col]
// h broadcast: [parity][hi/lo][b*512] bf16
__device__ __align__(16) __nv_bfloat16 g_hbuf[2][2][BB * UU];
// per-CTA packed recurrent-weight fragments: [(nt*32+kt)*32+lane][4]
// words = {bhi0, bhi1, blo0, blo1}
__device__ __align__(16) uint32_t g_Bfrag[NCTA][8192];
// phase-1 split operands
__device__ __align__(16) __nv_bfloat16 g_xhl[2][(size_t)BB * TT * FF]; // [b][t][f]
__device__ __align__(16) __nv_bfloat16 g_wt[2][(size_t)G4 * FF];       // [n][k]
__device__ unsigned g_barcount;

// ---------------- helpers ----------------
__device__ __forceinline__ uint32_t smem_u32(const void* p) {
    uint32_t a;
    asm("{ .reg .u64 t; cvta.to.shared.u64 t, %1; cvt.u32.u64 %0, t; }"
        : "=r"(a) : "l"(p));
    return a;
}
__device__ __forceinline__ void cp_async16(uint32_t saddr, const void* gaddr) {
    asm volatile("cp.async.cg.shared.global [%0], [%1], 16;" :: "r"(saddr), "l"(gaddr));
}
#define CP_COMMIT() asm volatile("cp.async.commit_group;")
#define CP_WAIT0()  asm volatile("cp.async.wait_group 0;" ::: "memory")

__device__ __forceinline__ void mma_bf16(float c[4], uint32_t a0, uint32_t a1,
                                         uint32_t a2, uint32_t a3,
                                         uint32_t b0, uint32_t b1) {
    asm volatile(
        "mma.sync.aligned.m16n8k16.row.col.f32.bf16.bf16.f32 "
        "{%0,%1,%2,%3}, {%4,%5,%6,%7}, {%8,%9}, {%0,%1,%2,%3};"
        : "+f"(c[0]), "+f"(c[1]), "+f"(c[2]), "+f"(c[3])
        : "r"(a0), "r"(a1), "r"(a2), "r"(a3), "r"(b0), "r"(b1));
}
__device__ __forceinline__ uint4 ldsm4(uint32_t saddr) {
    uint4 r;
    asm volatile("ldmatrix.sync.aligned.m8n8.x4.shared.b16 {%0,%1,%2,%3}, [%4];"
                 : "=r"(r.x), "=r"(r.y), "=r"(r.z), "=r"(r.w) : "r"(saddr));
    return r;
}
__device__ __forceinline__ void split_bf16(float v, uint16_t& hi, uint16_t& lo) {
    __nv_bfloat16 h = __float2bfloat16(v);
    __nv_bfloat16 l = __float2bfloat16(v - __bfloat162float(h));
    hi = *(uint16_t*)&h; lo = *(uint16_t*)&l;
}

// ---------------- init ----------------
__global__ void init_kernel() {
    int i = blockIdx.x * blockDim.x + threadIdx.x;
    if (i == 0) g_barcount = 0u;
    uint32_t* p = (uint32_t*)g_hbuf;  // 65536 words
    for (int j = i; j < 65536; j += gridDim.x * blockDim.x) p[j] = 0u;
}

// ---------------- prep: split X (fp32 -> hi/lo bf16) ----------------
__global__ void prep_X(const float* __restrict__ x) {
    const size_t N = (size_t)BB * TT * FF;
    size_t stride = (size_t)gridDim.x * blockDim.x;
    for (size_t j = blockIdx.x * blockDim.x + threadIdx.x; j < N; j += stride) {
        uint16_t hi, lo;
        split_bf16(x[j], hi, lo);
        *(uint16_t*)&g_xhl[0][j] = hi;
        *(uint16_t*)&g_xhl[1][j] = lo;
    }
}

// ---------------- prep: split + transpose W -> [n][k] ----------------
__global__ void prep_W(const float* __restrict__ w) {
    const int N = G4 * FF;
    int stride = gridDim.x * blockDim.x;
    for (int j = blockIdx.x * blockDim.x + threadIdx.x; j < N; j += stride) {
        int n = j >> 8, k = j & 255;
        uint16_t hi, lo;
        split_bf16(w[(size_t)k * G4 + n], hi, lo);
        *(uint16_t*)&g_wt[0][j] = hi;
        *(uint16_t*)&g_wt[1][j] = lo;
    }
}

// ---------------- prep: recurrent weight fragments (packed) -------------
// CTA j owns units [4j,4j+4). n = nt*8 + g (g=lane>>2); gate = n>>2, u = n&3;
// global col = gate*512 + 4j + u.  k = kt*16 + tq*2 + w2*8 (tq=lane&3).
// word layout per (nt,kt,lane): {bhi(w2=0), bhi(w2=1), blo(w2=0), blo(w2=1)}
__global__ void prep_B(const float* __restrict__ R) {
    const int j = blockIdx.x;
    uint32_t* dst = g_Bfrag[j];
    for (int widx = threadIdx.x; widx < 8192; widx += blockDim.x) {
        int w     = widx & 3;
        int lane  = (widx >> 2) & 31;
        int kt    = (widx >> 7) & 31;
        int nt    = widx >> 12;
        int plane = w >> 1, w2 = w & 1;
        int g = lane >> 2, tq = lane & 3;
        int k = kt * 16 + tq * 2 + w2 * 8;
        int n = nt * 8 + g;
        int col = (n >> 2) * 512 + j * 4 + (n & 3);
        float v0 = R[(size_t)k * G4 + col];
        float v1 = R[(size_t)(k + 1) * G4 + col];
        uint16_t h0, l0, h1, l1;
        split_bf16(v0, h0, l0);
        split_bf16(v1, h1, l1);
        uint16_t a = plane ? l0 : h0, b = plane ? l1 : h1;
        dst[widx] = ((uint32_t)b << 16) | a;
    }
}

// ---------------- phase 1: xz = x @ kernel + bias  (mma.sync bf16 split) --
// C[M=65536][N=2048], K=256 in 2 chunks of 128. Tile 128x128, 256 thr.
#define X1_AS   272                      // smem row stride bytes (128 bf16 + pad)
#define X1_APL  34816                    // per-plane tile bytes (128*272)
#define X1_SMEM (4 * 34816)              // Ahi, Alo, Bhi, Blo

__global__ __launch_bounds__(256, 1) void xz_mma(const float* __restrict__ bias) {
    extern __shared__ char sm1[];
    const int tid  = threadIdx.x;
    const int lane = tid & 31;
    const int warp = tid >> 5;
    const int wm = warp >> 2, wn = warp & 3;
    const int mbase = blockIdx.y * 128, nbase = blockIdx.x * 128;
    const uint32_t smB = smem_u32(sm1);
    const uint32_t smAhi = smB, smAlo = smB + X1_APL;
    const uint32_t smBhi = smB + 2 * X1_APL, smBlo = smB + 3 * X1_APL;

    float c[4][4][4];
#pragma unroll
    for (int mi = 0; mi < 4; mi++)
#pragma unroll
        for (int ni = 0; ni < 4; ni++)
#pragma unroll
            for (int q = 0; q < 4; q++) c[mi][ni][q] = 0.f;

    // ldmatrix lane bases
    const int rowA = (lane & 7) + ((lane >> 3) & 1) * 8;
    const int kbA  = ((lane >> 4) & 1) * 16;
    const int mB   = lane >> 3;
    const int rowB = ((mB >> 1) & 1) * 8 + (lane & 7);
    const int kbB  = (mB & 1) * 16;

    // staging constants: thread handles rows (tid>>4)+16*s, kg = tid&15
    const int srow0 = tid >> 4;
    const int kg    = tid & 15;

    for (int ch = 0; ch < 2; ch++) {
        // ---- stage chunk: A rows (x), B rows (w^T), both planes ----
#pragma unroll
        for (int s = 0; s < 8; s++) {
            int row = srow0 + s * 16;
            int m = mbase + row;
            int b = m & 63, tt = m >> 6;
            size_t offA = ((size_t)(b << 10) + tt) * 256 + ch * 128 + kg * 8;
            uint32_t d = row * X1_AS + kg * 16;
            cp_async16(smAhi + d, &g_xhl[0][offA]);
            cp_async16(smAlo + d, &g_xhl[1][offA]);
            size_t offB = (size_t)(nbase + row) * 256 + ch * 128 + kg * 8;
            cp_async16(smBhi + d, &g_wt[0][offB]);
            cp_async16(smBlo + d, &g_wt[1][offB]);
        }
        CP_COMMIT(); CP_WAIT0();
        __syncthreads();

#pragma unroll
        for (int kt = 0; kt < 8; kt++) {
            uint4 ah[4], al[4];
#pragma unroll
            for (int mi = 0; mi < 4; mi++) {
                uint32_t ar = (wm * 64 + mi * 16 + rowA) * X1_AS + kbA + kt * 32;
                ah[mi] = ldsm4(smAhi + ar);
                al[mi] = ldsm4(smAlo + ar);
            }
            uint32_t br0 = (wn * 32 + rowB) * X1_AS + kbB + kt * 32;
            uint32_t br1 = (wn * 32 + 16 + rowB) * X1_AS + kbB + kt * 32;
            uint4 bh01 = ldsm4(smBhi + br0);
            uint4 bh23 = ldsm4(smBhi + br1);
            uint4 bl01 = ldsm4(smBlo + br0);
            uint4 bl23 = ldsm4(smBlo + br1);
#pragma unroll
            for (int mi = 0; mi < 4; mi++) {
                mma_bf16(c[mi][0], ah[mi].x, ah[mi].y, ah[mi].z, ah[mi].w, bh01.x, bh01.y);
                mma_bf16(c[mi][0], ah[mi].x, ah[mi].y, ah[mi].z, ah[mi].w, bl01.x, bl01.y);
                mma_bf16(c[mi][0], al[mi].x, al[mi].y, al[mi].z, al[mi].w, bh01.x, bh01.y);
                mma_bf16(c[mi][1], ah[mi].x, ah[mi].y, ah[mi].z, ah[mi].w, bh01.z, bh01.w);
                mma_bf16(c[mi][1], ah[mi].x, ah[mi].y, ah[mi].z, ah[mi].w, bl01.z, bl01.w);
                mma_bf16(c[mi][1], al[mi].x, al[mi].y, al[mi].z, al[mi].w, bh01.z, bh01.w);
                mma_bf16(c[mi][2], ah[mi].x, ah[mi].y, ah[mi].z, ah[mi].w, bh23.x, bh23.y);
                mma_bf16(c[mi][2], ah[mi].x, ah[mi].y, ah[mi].z, ah[mi].w, bl23.x, bl23.y);
                mma_bf16(c[mi][2], al[mi].x, al[mi].y, al[mi].z, al[mi].w, bh23.x, bh23.y);
                mma_bf16(c[mi][3], ah[mi].x, ah[mi].y, ah[mi].z, ah[mi].w, bh23.z, bh23.w);
                mma_bf16(c[mi][3], ah[mi].x, ah[mi].y, ah[mi].z, ah[mi].w, bl23.z, bl23.w);
                mma_bf16(c[mi][3], al[mi].x, al[mi].y, al[mi].z, al[mi].w, bh23.z, bh23.w);
            }
        }
        __syncthreads();
    }

    // ---- epilogue: add bias, store fp32 ----
    const int g = lane >> 2, tq = lane & 3;
#pragma unroll
    for (int ni = 0; ni < 4; ni++) {
        int col = nbase + wn * 32 + ni * 8 + tq * 2;
        float bx = bias[col], by = bias[col + 1];
#pragma unroll
        for (int mi = 0; mi < 4; mi++) {
            int row = mbase + wm * 64 + mi * 16 + g;
            float2 v0 = {c[mi][ni][0] + bx, c[mi][ni][1] + by};
            float2 v1 = {c[mi][ni][2] + bx, c[mi][ni][3] + by};
            *(float2*)&g_xz[(size_t)row * G4 + col] = v0;
            *(float2*)&g_xz[(size_t)(row + 8) * G4 + col] = v1;
        }
    }
}

// ---------------- phase 2: persistent mma.sync recurrence ----------------
// SMEM map (bytes, relative to dynamic base):
#define H_STRIDE   1040                 // 520 bf16/row (4-bank row shift)
#define SM_HHI     0
#define SM_HLO     66560                // 64*1040
#define SM_B       133120               // packed B frags, 32KB
#define SM_Z       165888               // zbuf: [4 kq][64][20] f32
#define Z_S        20
#define SMEM_DYN   186368

__global__ __launch_bounds__(THR2, 1) void lstm_rec(float* __restrict__ out)
{
    extern __shared__ char sm[];
    const int tid  = threadIdx.x;
    const int lane = tid & 31;
    const int warp = tid >> 5;
    const int cta  = blockIdx.x;
    const int kq = warp >> 2;           // k-quarter 0..3
    const int mt = warp & 3;            // batch tile 0..3

    const uint32_t smBase = smem_u32(sm);

    // ---- load resident B fragments (32KB) ----
    {
        const uint32_t* src = g_Bfrag[cta];
        for (int i = tid; i < 2048; i += THR2)
            cp_async16(smBase + SM_B + i * 16, src + i * 4);
        CP_COMMIT(); CP_WAIT0();
    }
    __syncthreads();

    // ---- h-staging constants (kq group stages its own k slice) ----
    const int gi = tid & 127;
    const uint32_t dstB = (uint32_t)((gi >> 4) * H_STRIDE + (kq * 16 + (gi & 15)) * 16);
    const int srcB = (gi >> 4) * 512 + (kq * 16 + (gi & 15)) * 8;   // elems

    // ---- ldmatrix / LDS lane bases ----
    const int rowA = (lane & 7) + ((lane >> 3) & 1) * 8;
    const int kbA  = ((lane >> 4) & 1) * 16;
    const uint32_t aHiBase = smBase + SM_HHI + (mt * 16 + rowA) * H_STRIDE + kbA;
    const uint32_t aLoBase = smBase + SM_HLO + (mt * 16 + rowA) * H_STRIDE + kbA;
    float* zb = (float*)(sm + SM_Z);
    const int g = lane >> 2, tq = lane & 3;

    float cst[4] = {0.f, 0.f, 0.f, 0.f};

    for (int t = 0; t < TT; t++) {
        const int p = t & 1;

        // xz prefetch for epilogue threads
        float4 xz4[4];
        if (tid < 64) {
            const float* xzt = &g_xz[((size_t)t * BB + tid) * G4 + cta * 4];
#pragma unroll
            for (int gate = 0; gate < 4; gate++)
                xz4[gate] = *(const float4*)&xzt[gate * 512];
        }

        // stage this kq-group's k slice of h (hi+lo)
        {
            const __nv_bfloat16* hhi = g_hbuf[p][0];
            const __nv_bfloat16* hlo = g_hbuf[p][1];
#pragma unroll
            for (int s = 0; s < 8; s++) {
                cp_async16(smBase + SM_HHI + dstB + s * 8 * H_STRIDE,
                           hhi + srcB + s * 8 * 512);
                cp_async16(smBase + SM_HLO + dstB + s * 8 * H_STRIDE,
                           hlo + srcB + s * 8 * 512);
            }
            CP_COMMIT(); CP_WAIT0();
        }
        // kq-group barrier (128 threads each; warps of a group are contiguous)
        asm volatile("bar.sync %0, 128;" :: "r"(kq + 1) : "memory");

        // ---- mma: 8 ktiles (this warp's k-quarter), 2 nt, 3 split terms ---
        float c[2][4];
#pragma unroll
        for (int nt = 0; nt < 2; nt++)
#pragma unroll
            for (int q = 0; q < 4; q++) c[nt][q] = 0.f;

#pragma unroll
        for (int ktl = 0; ktl < 8; ktl++) {
            const int kt = kq * 8 + ktl;
            uint4 ah = ldsm4(aHiBase + kt * 32);
            uint4 al = ldsm4(aLoBase + kt * 32);
#pragma unroll
            for (int nt = 0; nt < 2; nt++) {
                uint4 bb = *(const uint4*)(sm + SM_B + (nt * 32 + kt) * 512 + lane * 16);
                mma_bf16(c[nt], ah.x, ah.y, ah.z, ah.w, bb.x, bb.y);  // AhiBhi
                mma_bf16(c[nt], ah.x, ah.y, ah.z, ah.w, bb.z, bb.w);  // AhiBlo
                mma_bf16(c[nt], al.x, al.y, al.z, al.w, bb.x, bb.y);  // AloBhi
            }
        }

        // store partials: zbuf[kq][row][col]
#pragma unroll
        for (int nt = 0; nt < 2; nt++) {
            int r0 = mt * 16 + g, cc = nt * 8 + tq * 2;
            float2 v01 = {c[nt][0], c[nt][1]};
            float2 v23 = {c[nt][2], c[nt][3]};
            *(float2*)&zb[(kq * 64 + r0) * Z_S + cc] = v01;
            *(float2*)&zb[(kq * 64 + r0 + 8) * Z_S + cc] = v23;
        }
        __syncthreads();

        // ---- epilogue: threads 0..63, one per batch ----
        if (tid < 64) {
            float q[4][4];
#pragma unroll
            for (int gate = 0; gate < 4; gate++) {
                q[gate][0] = xz4[gate].x; q[gate][1] = xz4[gate].y;
                q[gate][2] = xz4[gate].z; q[gate][3] = xz4[gate].w;
#pragma unroll
                for (int kk = 0; kk < 4; kk++) {
                    float4 z = *(const float4*)&zb[(kk * 64 + tid) * Z_S + gate * 4];
                    q[gate][0] += z.x; q[gate][1] += z.y;
                    q[gate][2] += z.z; q[gate][3] += z.w;
                }
            }
            uint16_t hh[4], hl[4];
            float ov[4];
#pragma unroll
            for (int u = 0; u < 4; u++) {
                float ig = 1.f / (1.f + __expf(-q[0][u]));
                float fg = 1.f / (1.f + __expf(-q[1][u]));
                float og = 1.f / (1.f + __expf(-q[3][u]));
                cst[u] = fg * cst[u] + ig * q[2][u];
                float h = og * cst[u];
                split_bf16(h, hh[u], hl[u]);
                ov[u] = tanhf(h);
            }
            uint2 vhi, vlo;
            vhi.x = ((uint32_t)hh[1] << 16) | hh[0];
            vhi.y = ((uint32_t)hh[3] << 16) | hh[2];
            vlo.x = ((uint32_t)hl[1] << 16) | hl[0];
            vlo.y = ((uint32_t)hl[3] << 16) | hl[2];
            const int pn = p ^ 1;
            __stcg((uint2*)&g_hbuf[pn][0][tid * UU + cta * 4], vhi);
            __stcg((uint2*)&g_hbuf[pn][1][tid * UU + cta * 4], vlo);
            float4 o4 = {ov[0], ov[1], ov[2], ov[3]};
            *(float4*)&out[((size_t)tid * TT + t) * UU + cta * 4] = o4;
        }

        // ---- grid barrier (monotonic counter) ----
        __syncthreads();
        if (tid == 0) {
            __threadfence();
            unsigned arrived = atomicAdd(&g_barcount, 1u) + 1u;
            unsigned target = (unsigned)(t + 1) * (unsigned)NCTA;
            if (arrived < target) {
                while (*((volatile unsigned*)&g_barcount) < target) { }
            }
        }
        __syncthreads();
    }
}

// ---------------- launch ----------------
extern "C" void kernel_launch(void* const* d_in, const int* in_sizes, int n_in,
                              void* d_out, int out_size) {
    const float* x    = (const float*)d_in[0];   // [64,1024,256]
    const float* w    = (const float*)d_in[1];   // [256,2048]
    const float* rw   = (const float*)d_in[2];   // [512,2048]
    const float* bias = (const float*)d_in[3];   // [2048]
    float* out = (float*)d_out;                  // [64,1024,512]
    (void)in_sizes; (void)n_in; (void)out_size;

    init_kernel<<<64, 256>>>();
    prep_X<<<4096, 256>>>(x);
    prep_W<<<512, 256>>>(w);
    prep_B<<<NCTA, 256>>>(rw);

    static int smem_set = 0;
    if (!smem_set) {
        cudaFuncSetAttribute(xz_mma, cudaFuncAttributeMaxDynamicSharedMemorySize,
                             X1_SMEM);
        cudaFuncSetAttribute(lstm_rec, cudaFuncAttributeMaxDynamicSharedMemorySize,
                             SMEM_DYN);
        smem_set = 1;
    }

    dim3 g1(G4 / 128, (BB * TT) / 128);   // (16, 512)
    xz_mma<<<g1, 256, X1_SMEM>>>(bias);

    lstm_rec<<<NCTA, THR2, SMEM_DYN>>>(out);
}

// round 7
// speedup vs baseline: 2.3455x; 1.2090x over previous
#include <cuda_runtime.h>
#include <cuda_bf16.h>
#include <math.h>
#include <stdint.h>

// Problem dims (fixed by the dataset)
#define BB 64
#define TT 1024
#define FF 256
#define UU 512
#define G4 2048   // 4*U

#define NCTA 128          // phase-2 CTAs (1/SM, co-resident)
#define THR2 512          // 16 warps

// ---------------- device scratch (no cudaMalloc allowed) ----------------
__device__ float g_xz[(size_t)TT * BB * G4];                 // [t][b][col]
// h broadcast images, XOR-swizzled: [parity][hi/lo][64 rows x 1024B]
// byte offset = row*1024 + ((col16 ^ (row&7))<<4) + within16
__device__ __align__(16) unsigned char g_hbuf[2][2][BB * 1024];
// per-CTA packed recurrent-weight fragments: [(nt*32+kt)*32+lane][4]
// words = {bhi0, bhi1, blo0, blo1}
__device__ __align__(16) uint32_t g_Bfrag[NCTA][8192];
// phase-1 split operands
__device__ __align__(16) __nv_bfloat16 g_xhl[2][(size_t)BB * TT * FF]; // [b][t][f]
__device__ __align__(16) __nv_bfloat16 g_wt[2][(size_t)G4 * FF];       // [n][k]
__device__ unsigned g_barcount;

// ---------------- helpers ----------------
__device__ __forceinline__ uint32_t smem_u32(const void* p) {
    uint32_t a;
    asm("{ .reg .u64 t; cvta.to.shared.u64 t, %1; cvt.u32.u64 %0, t; }"
        : "=r"(a) : "l"(p));
    return a;
}
__device__ __forceinline__ void cp_async16(uint32_t saddr, const void* gaddr) {
    asm volatile("cp.async.cg.shared.global [%0], [%1], 16;" :: "r"(saddr), "l"(gaddr));
}
#define CP_COMMIT() asm volatile("cp.async.commit_group;")
#define CP_WAIT0()  asm volatile("cp.async.wait_group 0;" ::: "memory")

// bulk async copy global->shared, completes on mbarrier (sm_90 base ISA)
__device__ __forceinline__ void bulk_g2s(uint32_t dst, const void* src,
                                         uint32_t bytes, uint32_t mbar) {
    asm volatile(
        "cp.async.bulk.shared::cluster.global.mbarrier::complete_tx::bytes "
        "[%0], [%1], %2, [%3];"
        :: "r"(dst), "l"(src), "r"(bytes), "r"(mbar) : "memory");
}
#define MBAR_INIT(mbar, cnt) \
    asm volatile("mbarrier.init.shared.b64 [%0], %1;" :: "r"(mbar), "r"(cnt) : "memory")
#define MBAR_EXPECT_TX(mbar, bytes) \
    asm volatile("mbarrier.arrive.expect_tx.shared.b64 _, [%0], %1;" \
                 :: "r"(mbar), "r"(bytes) : "memory")

__device__ __forceinline__ void mbar_wait(uint32_t mbar, uint32_t parity) {
    asm volatile(
        "{\n\t.reg .pred P1;\n\t"
        "WL_%=:\n\t"
        "mbarrier.try_wait.parity.acquire.cta.shared::cta.b64 P1, [%0], %1, 0x989680;\n\t"
        "@P1 bra.uni WD_%=;\n\t"
        "bra.uni WL_%=;\n\t"
        "WD_%=:\n\t}"
        :: "r"(mbar), "r"(parity) : "memory");
}

__device__ __forceinline__ void mma_bf16(float c[4], uint32_t a0, uint32_t a1,
                                         uint32_t a2, uint32_t a3,
                                         uint32_t b0, uint32_t b1) {
    asm volatile(
        "mma.sync.aligned.m16n8k16.row.col.f32.bf16.bf16.f32 "
        "{%0,%1,%2,%3}, {%4,%5,%6,%7}, {%8,%9}, {%0,%1,%2,%3};"
        : "+f"(c[0]), "+f"(c[1]), "+f"(c[2]), "+f"(c[3])
        : "r"(a0), "r"(a1), "r"(a2), "r"(a3), "r"(b0), "r"(b1));
}
__device__ __forceinline__ uint4 ldsm4(uint32_t saddr) {
    uint4 r;
    asm volatile("ldmatrix.sync.aligned.m8n8.x4.shared.b16 {%0,%1,%2,%3}, [%4];"
                 : "=r"(r.x), "=r"(r.y), "=r"(r.z), "=r"(r.w) : "r"(saddr));
    return r;
}
__device__ __forceinline__ void split_bf16(float v, uint16_t& hi, uint16_t& lo) {
    __nv_bfloat16 h = __float2bfloat16(v);
    __nv_bfloat16 l = __float2bfloat16(v - __bfloat162float(h));
    hi = *(uint16_t*)&h; lo = *(uint16_t*)&l;
}

// ---------------- init ----------------
__global__ void init_kernel() {
    int i = blockIdx.x * blockDim.x + threadIdx.x;
    if (i == 0) g_barcount = 0u;
    uint32_t* p = (uint32_t*)g_hbuf;  // 2*2*64*1024 bytes = 65536 words
    for (int j = i; j < 65536; j += gridDim.x * blockDim.x) p[j] = 0u;
}

// ---------------- prep: split X (fp32 -> hi/lo bf16) ----------------
__global__ void prep_X(const float* __restrict__ x) {
    const size_t N = (size_t)BB * TT * FF;
    size_t stride = (size_t)gridDim.x * blockDim.x;
    for (size_t j = blockIdx.x * blockDim.x + threadIdx.x; j < N; j += stride) {
        uint16_t hi, lo;
        split_bf16(x[j], hi, lo);
        *(uint16_t*)&g_xhl[0][j] = hi;
        *(uint16_t*)&g_xhl[1][j] = lo;
    }
}

// ---------------- prep: split + transpose W -> [n][k] ----------------
__global__ void prep_W(const float* __restrict__ w) {
    const int N = G4 * FF;
    int stride = gridDim.x * blockDim.x;
    for (int j = blockIdx.x * blockDim.x + threadIdx.x; j < N; j += stride) {
        int n = j >> 8, k = j & 255;
        uint16_t hi, lo;
        split_bf16(w[(size_t)k * G4 + n], hi, lo);
        *(uint16_t*)&g_wt[0][j] = hi;
        *(uint16_t*)&g_wt[1][j] = lo;
    }
}

// ---------------- prep: recurrent weight fragments (packed) -------------
__global__ void prep_B(const float* __restrict__ R) {
    const int j = blockIdx.x;
    uint32_t* dst = g_Bfrag[j];
    for (int widx = threadIdx.x; widx < 8192; widx += blockDim.x) {
        int w     = widx & 3;
        int lane  = (widx >> 2) & 31;
        int kt    = (widx >> 7) & 31;
        int nt    = widx >> 12;
        int plane = w >> 1, w2 = w & 1;
        int g = lane >> 2, tq = lane & 3;
        int k = kt * 16 + tq * 2 + w2 * 8;
        int n = nt * 8 + g;
        int col = (n >> 2) * 512 + j * 4 + (n & 3);
        float v0 = R[(size_t)k * G4 + col];
        float v1 = R[(size_t)(k + 1) * G4 + col];
        uint16_t h0, l0, h1, l1;
        split_bf16(v0, h0, l0);
        split_bf16(v1, h1, l1);
        uint16_t a = plane ? l0 : h0, b = plane ? l1 : h1;
        dst[widx] = ((uint32_t)b << 16) | a;
    }
}

// ---------------- phase 1: xz = x @ kernel + bias  (mma.sync bf16 split) --
#define X1_AS   272
#define X1_APL  34816
#define X1_SMEM (4 * 34816)

__global__ __launch_bounds__(256, 1) void xz_mma(const float* __restrict__ bias) {
    extern __shared__ char sm1[];
    const int tid  = threadIdx.x;
    const int lane = tid & 31;
    const int warp = tid >> 5;
    const int wm = warp >> 2, wn = warp & 3;
    const int mbase = blockIdx.y * 128, nbase = blockIdx.x * 128;
    const uint32_t smB = smem_u32(sm1);
    const uint32_t smAhi = smB, smAlo = smB + X1_APL;
    const uint32_t smBhi = smB + 2 * X1_APL, smBlo = smB + 3 * X1_APL;

    float c[4][4][4];
#pragma unroll
    for (int mi = 0; mi < 4; mi++)
#pragma unroll
        for (int ni = 0; ni < 4; ni++)
#pragma unroll
            for (int q = 0; q < 4; q++) c[mi][ni][q] = 0.f;

    const int rowA = (lane & 7) + ((lane >> 3) & 1) * 8;
    const int kbA  = ((lane >> 4) & 1) * 16;
    const int mB   = lane >> 3;
    const int rowB = ((mB >> 1) & 1) * 8 + (lane & 7);
    const int kbB  = (mB & 1) * 16;
    const int srow0 = tid >> 4;
    const int kg    = tid & 15;

    for (int ch = 0; ch < 2; ch++) {
#pragma unroll
        for (int s = 0; s < 8; s++) {
            int row = srow0 + s * 16;
            int m = mbase + row;
            int b = m & 63, tt = m >> 6;
            size_t offA = ((size_t)(b << 10) + tt) * 256 + ch * 128 + kg * 8;
            uint32_t d = row * X1_AS + kg * 16;
            cp_async16(smAhi + d, &g_xhl[0][offA]);
            cp_async16(smAlo + d, &g_xhl[1][offA]);
            size_t offB = (size_t)(nbase + row) * 256 + ch * 128 + kg * 8;
            cp_async16(smBhi + d, &g_wt[0][offB]);
            cp_async16(smBlo + d, &g_wt[1][offB]);
        }
        CP_COMMIT(); CP_WAIT0();
        __syncthreads();

#pragma unroll
        for (int kt = 0; kt < 8; kt++) {
            uint4 ah[4], al[4];
#pragma unroll
            for (int mi = 0; mi < 4; mi++) {
                uint32_t ar = (wm * 64 + mi * 16 + rowA) * X1_AS + kbA + kt * 32;
                ah[mi] = ldsm4(smAhi + ar);
                al[mi] = ldsm4(smAlo + ar);
            }
            uint32_t br0 = (wn * 32 + rowB) * X1_AS + kbB + kt * 32;
            uint32_t br1 = (wn * 32 + 16 + rowB) * X1_AS + kbB + kt * 32;
            uint4 bh01 = ldsm4(smBhi + br0);
            uint4 bh23 = ldsm4(smBhi + br1);
            uint4 bl01 = ldsm4(smBlo + br0);
            uint4 bl23 = ldsm4(smBlo + br1);
#pragma unroll
            for (int mi = 0; mi < 4; mi++) {
                mma_bf16(c[mi][0], ah[mi].x, ah[mi].y, ah[mi].z, ah[mi].w, bh01.x, bh01.y);
                mma_bf16(c[mi][0], ah[mi].x, ah[mi].y, ah[mi].z, ah[mi].w, bl01.x, bl01.y);
                mma_bf16(c[mi][0], al[mi].x, al[mi].y, al[mi].z, al[mi].w, bh01.x, bh01.y);
                mma_bf16(c[mi][1], ah[mi].x, ah[mi].y, ah[mi].z, ah[mi].w, bh01.z, bh01.w);
                mma_bf16(c[mi][1], ah[mi].x, ah[mi].y, ah[mi].z, ah[mi].w, bl01.z, bl01.w);
                mma_bf16(c[mi][1], al[mi].x, al[mi].y, al[mi].z, al[mi].w, bh01.z, bh01.w);
                mma_bf16(c[mi][2], ah[mi].x, ah[mi].y, ah[mi].z, ah[mi].w, bh23.x, bh23.y);
                mma_bf16(c[mi][2], ah[mi].x, ah[mi].y, ah[mi].z, ah[mi].w, bl23.x, bl23.y);
                mma_bf16(c[mi][2], al[mi].x, al[mi].y, al[mi].z, al[mi].w, bh23.x, bh23.y);
                mma_bf16(c[mi][3], ah[mi].x, ah[mi].y, ah[mi].z, ah[mi].w, bh23.z, bh23.w);
                mma_bf16(c[mi][3], ah[mi].x, ah[mi].y, ah[mi].z, ah[mi].w, bl23.z, bl23.w);
                mma_bf16(c[mi][3], al[mi].x, al[mi].y, al[mi].z, al[mi].w, bh23.z, bh23.w);
            }
        }
        __syncthreads();
    }

    const int g = lane >> 2, tq = lane & 3;
#pragma unroll
    for (int ni = 0; ni < 4; ni++) {
        int col = nbase + wn * 32 + ni * 8 + tq * 2;
        float bx = bias[col], by = bias[col + 1];
#pragma unroll
        for (int mi = 0; mi < 4; mi++) {
            int row = mbase + wm * 64 + mi * 16 + g;
            float2 v0 = {c[mi][ni][0] + bx, c[mi][ni][1] + by};
            float2 v1 = {c[mi][ni][2] + bx, c[mi][ni][3] + by};
            *(float2*)&g_xz[(size_t)row * G4 + col] = v0;
            *(float2*)&g_xz[(size_t)(row + 8) * G4 + col] = v1;
        }
    }
}

// ---------------- phase 2: persistent mma.sync recurrence ----------------
// SMEM map (bytes, relative to dynamic base):
//   A hi image : [0, 64K)    64 rows x 1024B, XOR-swizzled (linear bulk copy)
//   A lo image : [64K, 128K)
//   B frags    : [128K, 160K)
//   zbuf       : [160K, +20480)  [4 kq][64][20] f32
#define SM_HHI     0
#define SM_HLO     65536
#define SM_B       131072
#define SM_Z       163840
#define Z_S        20
#define SMEM_DYN   184320

__global__ __launch_bounds__(THR2, 1) void lstm_rec(float* __restrict__ out)
{
    extern __shared__ char sm[];
    __shared__ __align__(8) uint64_t sh_mb[2];

    const int tid  = threadIdx.x;
    const int lane = tid & 31;
    const int warp = tid >> 5;
    const int cta  = blockIdx.x;
    const int kq = warp >> 2;           // k-quarter 0..3
    const int mt = warp & 3;            // batch tile 0..3

    const uint32_t smBase = smem_u32(sm);
    const uint32_t mb0 = smem_u32(&sh_mb[0]);
    const uint32_t mb1 = smem_u32(&sh_mb[1]);

    if (tid == 0) { MBAR_INIT(mb0, 1u); MBAR_INIT(mb1, 1u); }

    // ---- load resident B fragments (32KB) ----
    {
        const uint32_t* src = g_Bfrag[cta];
        for (int i = tid; i < 2048; i += THR2)
            cp_async16(smBase + SM_B + i * 16, src + i * 4);
        CP_COMMIT(); CP_WAIT0();
    }
    __syncthreads();

    // ---- ldmatrix lane bases (swizzled A image) ----
    const int rowA = (lane & 7) + ((lane >> 3) & 1) * 8;
    const int kbIdx = (lane >> 4) & 1;          // granule half within ktile
    const int arow  = mt * 16 + rowA;
    const uint32_t aRowHi = smBase + SM_HHI + arow * 1024;
    const uint32_t aRowLo = smBase + SM_HLO + arow * 1024;
    const uint32_t rxor = (uint32_t)(arow & 7);
    float* zb = (float*)(sm + SM_Z);
    const int g = lane >> 2, tq = lane & 3;
    const uint32_t myMb = (mt < 2) ? mb0 : mb1;

    float cst[4] = {0.f, 0.f, 0.f, 0.f};

    for (int t = 0; t < TT; t++) {
        const int p = t & 1;

        // issue bulk copies of h (hi+lo), split by row-halves onto 2 mbars
        if (tid == 0) {
            MBAR_EXPECT_TX(mb0, 65536u);
            bulk_g2s(smBase + SM_HHI, &g_hbuf[p][0][0], 32768u, mb0);
            bulk_g2s(smBase + SM_HLO, &g_hbuf[p][1][0], 32768u, mb0);
            MBAR_EXPECT_TX(mb1, 65536u);
            bulk_g2s(smBase + SM_HHI + 32768, &g_hbuf[p][0][32768], 32768u, mb1);
            bulk_g2s(smBase + SM_HLO + 32768, &g_hbuf[p][1][32768], 32768u, mb1);
        }

        // xz prefetch for epilogue threads (overlaps bulk copy)
        float4 xz4[4];
        if (tid < 64) {
            const float* xzt = &g_xz[((size_t)t * BB + tid) * G4 + cta * 4];
#pragma unroll
            for (int gate = 0; gate < 4; gate++)
                xz4[gate] = *(const float4*)&xzt[gate * 512];
        }

        // wait for this warp's row-half of h
        mbar_wait(myMb, (uint32_t)(t & 1));

        // ---- mma: 8 ktiles (this warp's k-quarter), 2 nt, 3 split terms ---
        float c[2][4];
#pragma unroll
        for (int nt = 0; nt < 2; nt++)
#pragma unroll
            for (int q = 0; q < 4; q++) c[nt][q] = 0.f;

#pragma unroll
        for (int ktl = 0; ktl < 8; ktl++) {
            const int kt = kq * 8 + ktl;
            const uint32_t goff = (((uint32_t)(kt * 2 + kbIdx)) ^ rxor) << 4;
            uint4 ah = ldsm4(aRowHi + goff);
            uint4 al = ldsm4(aRowLo + goff);
#pragma unroll
            for (int nt = 0; nt < 2; nt++) {
                uint4 bb = *(const uint4*)(sm + SM_B + (nt * 32 + kt) * 512 + lane * 16);
                mma_bf16(c[nt], ah.x, ah.y, ah.z, ah.w, bb.x, bb.y);  // AhiBhi
                mma_bf16(c[nt], ah.x, ah.y, ah.z, ah.w, bb.z, bb.w);  // AhiBlo
                mma_bf16(c[nt], al.x, al.y, al.z, al.w, bb.x, bb.y);  // AloBhi
            }
        }

        // store partials: zbuf[kq][row][col]
#pragma unroll
        for (int nt = 0; nt < 2; nt++) {
            int r0 = mt * 16 + g, cc = nt * 8 + tq * 2;
            float2 v01 = {c[nt][0], c[nt][1]};
            float2 v23 = {c[nt][2], c[nt][3]};
            *(float2*)&zb[(kq * 64 + r0) * Z_S + cc] = v01;
            *(float2*)&zb[(kq * 64 + r0 + 8) * Z_S + cc] = v23;
        }
        __syncthreads();

        // ---- epilogue: threads 0..63, one per batch ----
        if (tid < 64) {
            float q[4][4];
#pragma unroll
            for (int gate = 0; gate < 4; gate++) {
                q[gate][0] = xz4[gate].x; q[gate][1] = xz4[gate].y;
                q[gate][2] = xz4[gate].z; q[gate][3] = xz4[gate].w;
#pragma unroll
                for (int kk = 0; kk < 4; kk++) {
                    float4 z = *(const float4*)&zb[(kk * 64 + tid) * Z_S + gate * 4];
                    q[gate][0] += z.x; q[gate][1] += z.y;
                    q[gate][2] += z.z; q[gate][3] += z.w;
                }
            }
            uint16_t hh[4], hl[4];
            float ov[4];
#pragma unroll
            for (int u = 0; u < 4; u++) {
                float ig = 1.f / (1.f + __expf(-q[0][u]));
                float fg = 1.f / (1.f + __expf(-q[1][u]));
                float og = 1.f / (1.f + __expf(-q[3][u]));
                cst[u] = fg * cst[u] + ig * q[2][u];
                float h = og * cst[u];
                split_bf16(h, hh[u], hl[u]);
                ov[u] = tanhf(h);
            }
            uint2 vhi, vlo;
            vhi.x = ((uint32_t)hh[1] << 16) | hh[0];
            vhi.y = ((uint32_t)hh[3] << 16) | hh[2];
            vlo.x = ((uint32_t)hl[1] << 16) | hl[0];
            vlo.y = ((uint32_t)hl[3] << 16) | hl[2];
            const int pn = p ^ 1;
            // swizzled global h-image store: row=tid, granule=(cta>>1)^(tid&7)
            uint32_t off = (uint32_t)tid * 1024 +
                           ((((uint32_t)cta >> 1) ^ ((uint32_t)tid & 7)) << 4) +
                           ((uint32_t)cta & 1) * 8;
            __stcg((uint2*)(&g_hbuf[pn][0][0] + off), vhi);
            __stcg((uint2*)(&g_hbuf[pn][1][0] + off), vlo);
            float4 o4 = {ov[0], ov[1], ov[2], ov[3]};
            *(float4*)&out[((size_t)tid * TT + t) * UU + cta * 4] = o4;
        }

        // ---- grid barrier (monotonic counter) ----
        __syncthreads();
        if (tid == 0) {
            __threadfence();
            unsigned arrived = atomicAdd(&g_barcount, 1u) + 1u;
            unsigned target = (unsigned)(t + 1) * (unsigned)NCTA;
            if (arrived < target) {
                while (*((volatile unsigned*)&g_barcount) < target) { }
            }
        }
        __syncthreads();
    }
}

// ---------------- launch ----------------
extern "C" void kernel_launch(void* const* d_in, const int* in_sizes, int n_in,
                              void* d_out, int out_size) {
    const float* x    = (const float*)d_in[0];   // [64,1024,256]
    const float* w    = (const float*)d_in[1];   // [256,2048]
    const float* rw   = (const float*)d_in[2];   // [512,2048]
    const float* bias = (const float*)d_in[3];   // [2048]
    float* out = (float*)d_out;                  // [64,1024,512]
    (void)in_sizes; (void)n_in; (void)out_size;

    init_kernel<<<64, 256>>>();
    prep_X<<<4096, 256>>>(x);
    prep_W<<<512, 256>>>(w);
    prep_B<<<NCTA, 256>>>(rw);

    static int smem_set = 0;
    if (!smem_set) {
        cudaFuncSetAttribute(xz_mma, cudaFuncAttributeMaxDynamicSharedMemorySize,
                             X1_SMEM);
        cudaFuncSetAttribute(lstm_rec, cudaFuncAttributeMaxDynamicSharedMemorySize,
                             SMEM_DYN);
        smem_set = 1;
    }

    dim3 g1(G4 / 128, (BB * TT) / 128);   // (16, 512)
    xz_mma<<<g1, 256, X1_SMEM>>>(bias);

    lstm_rec<<<NCTA, THR2, SMEM_DYN>>>(out);
}